// round 2
// baseline (speedup 1.0000x reference)
#include <cuda_runtime.h>
#include <math.h>

#define N_NODES 65536
#define B_G     128
#define N_PG    512
#define N_E     1048576
#define K_SEL   256
#define EPG     8192

// ---------------- scratch ----------------
__device__ int   g_deg[N_NODES];
__device__ int   g_off[N_NODES];
__device__ float g_dis[N_NODES];
__device__ int   g_csr[N_E];            // graph-LOCAL source indices
__device__ float g_h[(size_t)N_NODES * 384];
__device__ float g_read[B_G * 768];
__device__ float g_z1[B_G * 256];
__device__ float g_z2[B_G * 128];

// ---------------- fused preprocessing: one block per graph ----------------
__global__ void k_prep(const int* __restrict__ src, const int* __restrict__ dst) {
    __shared__ int degs[N_PG];
    __shared__ int curs[N_PG];
    __shared__ int csr[EPG];
    int g = blockIdx.x, t = threadIdx.x;     // 512 threads
    int nb = g * N_PG, eb = g * EPG;

    degs[t] = 0;
    __syncthreads();
    for (int e = t; e < EPG; e += N_PG) atomicAdd(&degs[dst[eb + e] - nb], 1);
    __syncthreads();

    int d = degs[t];
    curs[t] = d;
    __syncthreads();
    for (int off = 1; off < N_PG; off <<= 1) {
        int v = (t >= off) ? curs[t - off] : 0;
        __syncthreads();
        curs[t] += v;
        __syncthreads();
    }
    int excl = curs[t] - d;
    g_off[nb + t] = eb + excl;
    g_deg[nb + t] = d;
    g_dis[nb + t] = rsqrtf((float)(d + 1));
    curs[t] = excl;
    __syncthreads();

    for (int e = t; e < EPG; e += N_PG) {
        int dl = dst[eb + e] - nb;
        int p = atomicAdd(&curs[dl], 1);
        csr[p] = src[eb + e] - nb;           // local src
    }
    __syncthreads();
    for (int e = t; e < EPG; e += N_PG) g_csr[eb + e] = csr[e];
}

// ---------------- fused GCN layer: GEMM(512x64x128) + aggregate, per (graph, colhalf) ----------------
// grid (2, 128), block 512. Dynamic SMEM layout (floats):
//   Ws  [128][68]   @ 0       (8704)
//   As  [2][16][132]@ 8704    (4224)
//   dss [512]       @ 12928   (512)
//   xw  [512][68]   @ 13440   (34816)
// total 48256 floats = 193024 bytes
#define SM_WS  0
#define SM_AS  8704
#define SM_DSS 12928
#define SM_XW  13440
#define SM_LAYER_BYTES (48256 * 4)

__global__ void __launch_bounds__(512, 1)
k_layer(const float* __restrict__ A, int lda,
        const float* __restrict__ W, const float* __restrict__ bias,
        float* __restrict__ out) {
    extern __shared__ float sm[];
    float* smWs  = sm + SM_WS;
    float* smAs  = sm + SM_AS;
    float* smDSS = sm + SM_DSS;
    float* smXW  = sm + SM_XW;

    int g = blockIdx.y;
    int c0 = blockIdx.x * 64;
    int tid = threadIdx.x;
    int nb = g * N_PG;

    // stage W[:, c0:c0+64]
    for (int i = tid; i < 128 * 16; i += 512) {
        int r = i >> 4, c = (i & 15) << 2;
        *(float4*)&smWs[r * 68 + c] = *(const float4*)(W + r * 128 + c0 + c);
    }
    // stage dis
    for (int i = tid; i < N_PG; i += 512) smDSS[i] = g_dis[nb + i];

    const float* Ag = A + (size_t)nb * lda;

    int tx = tid & 15, ty = tid >> 4;        // tx: 16 x 4 cols, ty: 32 x 4 rows
    int l_row = tid >> 2;                    // loader: 0..127
    int l_cp  = (tid & 3) << 2;              // 0,4,8,12

    for (int mt = 0; mt < 4; mt++) {
        const float* Ap = Ag + (size_t)(mt * 128 + l_row) * lda + l_cp;

        // preload k0 = 0 into buffer 0
        {
            float4 v = *(const float4*)Ap;
            float* dA = smAs + l_cp * 132 + l_row;
            dA[0] = v.x; dA[132] = v.y; dA[264] = v.z; dA[396] = v.w;
        }
        __syncthreads();

        float acc[4][4];
#pragma unroll
        for (int i = 0; i < 4; i++)
#pragma unroll
            for (int j = 0; j < 4; j++) acc[i][j] = 0.f;

#pragma unroll
        for (int k0 = 0; k0 < 128; k0 += 16) {
            int buf = (k0 >> 4) & 1;
            bool pf = (k0 < 112);
            float4 nxt;
            if (pf) nxt = *(const float4*)(Ap + k0 + 16);

            const float* Ab = smAs + buf * 2112;
#pragma unroll
            for (int kk = 0; kk < 16; kk++) {
                float a[4], b[4];
                *(float4*)a = *(const float4*)(Ab + kk * 132 + ty * 4);
                *(float4*)b = *(const float4*)&smWs[(k0 + kk) * 68 + tx * 4];
#pragma unroll
                for (int i = 0; i < 4; i++)
#pragma unroll
                    for (int j = 0; j < 4; j++) acc[i][j] += a[i] * b[j];
            }
            if (pf) {
                float* dA = smAs + (buf ^ 1) * 2112 + l_cp * 132 + l_row;
                dA[0] = nxt.x; dA[132] = nxt.y; dA[264] = nxt.z; dA[396] = nxt.w;
            }
            __syncthreads();
        }
#pragma unroll
        for (int i = 0; i < 4; i++) {
            float4 o = make_float4(acc[i][0], acc[i][1], acc[i][2], acc[i][3]);
            *(float4*)&smXW[(mt * 128 + ty * 4 + i) * 68 + tx * 4] = o;
        }
        __syncthreads();
    }

    // ---- aggregate from SMEM: out[n,c] = relu(bias + dn^2*xw[n] + dn*sum dis[s]*xw[s]) ----
    int cg = tid & 7;            // 8 col groups x 8 cols
    int ng = tid >> 3;           // 64 node groups x 8 nodes
    float4 bb0 = *(const float4*)(bias + c0 + cg * 8);
    float4 bb1 = *(const float4*)(bias + c0 + cg * 8 + 4);

    for (int ii = 0; ii < 8; ii++) {
        int n = ng * 8 + ii;
        float dn = smDSS[n];
        float s2 = dn * dn;
        const float* rn = smXW + n * 68 + cg * 8;
        float4 v0 = *(const float4*)rn;
        float4 v1 = *(const float4*)(rn + 4);
        float4 a0 = make_float4(s2 * v0.x, s2 * v0.y, s2 * v0.z, s2 * v0.w);
        float4 a1 = make_float4(s2 * v1.x, s2 * v1.y, s2 * v1.z, s2 * v1.w);

        int base = g_off[nb + n];
        int d = g_deg[nb + n];
        if (d > 0) {
            int s = g_csr[base];
            float w = dn * smDSS[s];
            const float* r = smXW + s * 68 + cg * 8;
            float4 u0 = *(const float4*)r;
            float4 u1 = *(const float4*)(r + 4);
            for (int j = 0; j < d; j++) {
                float wj = w;
                float4 t0 = u0, t1 = u1;
                if (j + 1 < d) {
                    int s2i = g_csr[base + j + 1];
                    w = dn * smDSS[s2i];
                    const float* r2 = smXW + s2i * 68 + cg * 8;
                    u0 = *(const float4*)r2;
                    u1 = *(const float4*)(r2 + 4);
                }
                a0.x += wj * t0.x; a0.y += wj * t0.y; a0.z += wj * t0.z; a0.w += wj * t0.w;
                a1.x += wj * t1.x; a1.y += wj * t1.y; a1.z += wj * t1.z; a1.w += wj * t1.w;
            }
        }
        float4 o0 = make_float4(fmaxf(a0.x + bb0.x, 0.f), fmaxf(a0.y + bb0.y, 0.f),
                                fmaxf(a0.z + bb0.z, 0.f), fmaxf(a0.w + bb0.w, 0.f));
        float4 o1 = make_float4(fmaxf(a1.x + bb1.x, 0.f), fmaxf(a1.y + bb1.y, 0.f),
                                fmaxf(a1.z + bb1.z, 0.f), fmaxf(a1.w + bb1.w, 0.f));
        float* op = out + (size_t)(nb + n) * 384 + c0 + cg * 8;
        *(float4*)op = o0;
        *(float4*)(op + 4) = o1;
    }
}

// ---------------- fused score GEMV + score aggregate + top-k + gated readout ----------------
__global__ void k_spool(const float* __restrict__ Wsc, const float* __restrict__ bs) {
    __shared__ float ws[384];
    __shared__ float spre[N_PG];
    __shared__ float dss[N_PG];
    __shared__ float scr[N_PG];
    __shared__ unsigned long long key[N_PG];
    __shared__ int sel[K_SEL];
    __shared__ float gate[K_SEL];

    int g = blockIdx.x, t = threadIdx.x;    // 512 threads
    int nb = g * N_PG;
    if (t < 384) ws[t] = Wsc[t];
    dss[t] = g_dis[nb + t];
    __syncthreads();

    int w = t >> 5, lane = t & 31;
    for (int i = 0; i < 32; i++) {
        int n = i * 16 + w;
        const float* h = g_h + (size_t)(nb + n) * 384;
        float acc = 0.f;
#pragma unroll
        for (int c = lane * 4; c < 384; c += 128) {
            float4 hv = *(const float4*)(h + c);
            float4 wv = *(const float4*)(ws + c);
            acc += hv.x * wv.x + hv.y * wv.y + hv.z * wv.z + hv.w * wv.w;
        }
#pragma unroll
        for (int o = 16; o; o >>= 1) acc += __shfl_xor_sync(0xffffffffu, acc, o);
        if (lane == 0) spre[n] = acc;
    }
    __syncthreads();

    float dn = dss[t];
    float sc = dn * dn * spre[t];
    int base = g_off[nb + t], d = g_deg[nb + t];
    for (int j = 0; j < d; j++) {
        int s = g_csr[base + j];
        sc += dn * dss[s] * spre[s];
    }
    sc += bs[0];
    scr[t] = sc;

    unsigned u = __float_as_uint(sc);
    u = (u & 0x80000000u) ? ~u : (u ^ 0x80000000u);
    u = ~u;                                  // descending order
    key[t] = ((unsigned long long)u << 32) | (unsigned)t;
    __syncthreads();

    for (int k = 2; k <= N_PG; k <<= 1) {
        for (int j = k >> 1; j > 0; j >>= 1) {
            int ixj = t ^ j;
            if (ixj > t) {
                unsigned long long a = key[t], b = key[ixj];
                bool up = ((t & k) == 0);
                if ((a > b) == up) { key[t] = b; key[ixj] = a; }
            }
            __syncthreads();
        }
    }

    if (t < K_SEL) {
        int idx = (int)(key[t] & 0xffffffffu);
        sel[t] = idx;
        gate[t] = tanhf(scr[idx]);
    }
    __syncthreads();

    if (t < 384) {
        float vmax = __int_as_float(0xff800000);
        float vsum = 0.f;
        const float* hb = g_h + (size_t)nb * 384;
        for (int i = 0; i < K_SEL; i++) {
            float v = hb[(size_t)sel[i] * 384 + t] * gate[i];
            vmax = fmaxf(vmax, v);
            vsum += v;
        }
        g_read[g * 768 + t] = vmax;
        g_read[g * 768 + 384 + t] = vsum * (1.0f / K_SEL);
    }
}

// ---------------- small SGEMM (MLP head): C = A(MxK)*B(KxN), bias+relu ----------------
__global__ void k_sgemm_br(const float* __restrict__ A, int lda,
                           const float* __restrict__ B, int ldb,
                           const float* __restrict__ bias,
                           float* __restrict__ C, int ldc, int Kdim) {
    __shared__ float As[16][68];
    __shared__ float Bs[16][68];
    int tid = threadIdx.x;
    int tx = tid & 15, ty = tid >> 4;
    int arow = tid >> 2, acol = (tid & 3) * 4;
    int brow = tid >> 4, bcol = (tid & 15) * 4;
    int row0 = blockIdx.y * 64, col0 = blockIdx.x * 64;
    const float* Aptr = A + (size_t)(row0 + arow) * lda + acol;
    const float* Bptr = B + (size_t)brow * ldb + col0 + bcol;
    float acc[4][4];
#pragma unroll
    for (int i = 0; i < 4; i++)
#pragma unroll
        for (int j = 0; j < 4; j++) acc[i][j] = 0.f;
    for (int k0 = 0; k0 < Kdim; k0 += 16) {
        float4 a = *(const float4*)(Aptr + k0);
        float4 b = *(const float4*)(Bptr + (size_t)k0 * ldb);
        As[acol + 0][arow] = a.x; As[acol + 1][arow] = a.y;
        As[acol + 2][arow] = a.z; As[acol + 3][arow] = a.w;
        *(float4*)&Bs[brow][bcol] = b;
        __syncthreads();
#pragma unroll
        for (int k = 0; k < 16; k++) {
            float ar[4], br[4];
            *(float4*)ar = *(const float4*)&As[k][ty * 4];
            *(float4*)br = *(const float4*)&Bs[k][tx * 4];
#pragma unroll
            for (int i = 0; i < 4; i++)
#pragma unroll
                for (int j = 0; j < 4; j++) acc[i][j] += ar[i] * br[j];
        }
        __syncthreads();
    }
#pragma unroll
    for (int i = 0; i < 4; i++)
#pragma unroll
        for (int j = 0; j < 4; j++) {
            int col = col0 + tx * 4 + j;
            C[(size_t)(row0 + ty * 4 + i) * ldc + col] =
                fmaxf(acc[i][j] + bias[col], 0.f);
        }
}

// ---------------- final layer + log_softmax ----------------
__global__ void k_final(const float* __restrict__ Wl3, const float* __restrict__ bl3,
                        float* __restrict__ out) {
    int r = blockIdx.x;
    int lane = threadIdx.x;
    float4 zv = *(const float4*)(g_z2 + r * 128 + lane * 4);
    float logits[10];
#pragma unroll
    for (int o = 0; o < 10; o++) {
        int k = lane * 4;
        float p = zv.x * Wl3[(k + 0) * 10 + o] + zv.y * Wl3[(k + 1) * 10 + o] +
                  zv.z * Wl3[(k + 2) * 10 + o] + zv.w * Wl3[(k + 3) * 10 + o];
#pragma unroll
        for (int s = 16; s; s >>= 1) p += __shfl_xor_sync(0xffffffffu, p, s);
        logits[o] = p + bl3[o];
    }
    if (lane == 0) {
        float m = logits[0];
#pragma unroll
        for (int o = 1; o < 10; o++) m = fmaxf(m, logits[o]);
        float se = 0.f;
#pragma unroll
        for (int o = 0; o < 10; o++) se += expf(logits[o] - m);
        float lse = m + logf(se);
#pragma unroll
        for (int o = 0; o < 10; o++) out[r * 10 + o] = logits[o] - lse;
    }
}

// ---------------- launcher ----------------
extern "C" void kernel_launch(void* const* d_in, const int* in_sizes, int n_in,
                              void* d_out, int out_size) {
    const float* x   = (const float*)d_in[0];
    const int*   ei  = (const int*)d_in[1];
    const float* W1  = (const float*)d_in[2];
    const float* b1  = (const float*)d_in[3];
    const float* W2  = (const float*)d_in[4];
    const float* b2  = (const float*)d_in[5];
    const float* W3  = (const float*)d_in[6];
    const float* b3  = (const float*)d_in[7];
    const float* Ws  = (const float*)d_in[8];
    const float* bs  = (const float*)d_in[9];
    const float* Wl1 = (const float*)d_in[10];
    const float* bl1 = (const float*)d_in[11];
    const float* Wl2 = (const float*)d_in[12];
    const float* bl2 = (const float*)d_in[13];
    const float* Wl3 = (const float*)d_in[14];
    const float* bl3 = (const float*)d_in[15];

    const int* src = ei;
    const int* dst = ei + N_E;

    static int attr_done = 0;
    if (!attr_done) {
        cudaFuncSetAttribute(k_layer, cudaFuncAttributeMaxDynamicSharedMemorySize,
                             SM_LAYER_BYTES);
        attr_done = 1;
    }

    void* p;
    cudaGetSymbolAddress(&p, g_h);    float* h  = (float*)p;
    cudaGetSymbolAddress(&p, g_read); float* rd = (float*)p;
    cudaGetSymbolAddress(&p, g_z1);   float* z1 = (float*)p;
    cudaGetSymbolAddress(&p, g_z2);   float* z2 = (float*)p;

    k_prep<<<B_G, N_PG>>>(src, dst);

    dim3 gl(2, B_G);
    k_layer<<<gl, 512, SM_LAYER_BYTES>>>(x,       128, W1, b1, h + 0);
    k_layer<<<gl, 512, SM_LAYER_BYTES>>>(h + 0,   384, W2, b2, h + 128);
    k_layer<<<gl, 512, SM_LAYER_BYTES>>>(h + 128, 384, W3, b3, h + 256);

    k_spool<<<B_G, N_PG>>>(Ws, bs);

    k_sgemm_br<<<dim3(4, 2), 256>>>(rd, 768, Wl1, 256, bl1, z1, 256, 768);
    k_sgemm_br<<<dim3(2, 2), 256>>>(z1, 256, Wl2, 128, bl2, z2, 128, 256);
    k_final<<<B_G, 32>>>(Wl3, bl3, (float*)d_out);
}

// round 3
// speedup vs baseline: 1.1773x; 1.1773x over previous
#include <cuda_runtime.h>
#include <cuda_bf16.h>
#include <math.h>
#include <stdint.h>

#define N_NODES 65536
#define B_G     128
#define N_PG    512
#define N_E     1048576
#define K_SEL   256
#define EPG     8192

// ---------------- scratch ----------------
__device__ int   g_deg[N_NODES];
__device__ int   g_off[N_NODES];
__device__ float g_dis[N_NODES];
__device__ int   g_csr[N_E];            // graph-LOCAL source indices
__device__ float g_xw[(size_t)N_NODES * 128];
__device__ float g_h[(size_t)N_NODES * 384];
__device__ float g_read[B_G * 768];
__device__ float g_z1[B_G * 256];
__device__ float g_z2[B_G * 128];

// ---------------- fused preprocessing: one block per graph ----------------
__global__ void k_prep(const int* __restrict__ src, const int* __restrict__ dst) {
    __shared__ int degs[N_PG];
    __shared__ int curs[N_PG];
    __shared__ int csr[EPG];
    int g = blockIdx.x, t = threadIdx.x;     // 512 threads
    int nb = g * N_PG, eb = g * EPG;

    degs[t] = 0;
    __syncthreads();
    for (int e = t; e < EPG; e += N_PG) atomicAdd(&degs[dst[eb + e] - nb], 1);
    __syncthreads();

    int d = degs[t];
    curs[t] = d;
    __syncthreads();
    for (int off = 1; off < N_PG; off <<= 1) {
        int v = (t >= off) ? curs[t - off] : 0;
        __syncthreads();
        curs[t] += v;
        __syncthreads();
    }
    int excl = curs[t] - d;
    g_off[nb + t] = eb + excl;
    g_deg[nb + t] = d;
    g_dis[nb + t] = rsqrtf((float)(d + 1));
    curs[t] = excl;
    __syncthreads();

    for (int e = t; e < EPG; e += N_PG) {
        int dl = dst[eb + e] - nb;
        int p = atomicAdd(&curs[dl], 1);
        csr[p] = src[eb + e] - nb;           // local src
    }
    __syncthreads();
    for (int e = t; e < EPG; e += N_PG) g_csr[eb + e] = csr[e];
}

// ---------------- tensor-core GEMM (bf16x3 split): C[M,128] = A[M,K=128] @ W[128,128] ----------------
// grid = M/128 blocks, 256 threads (8 warps), warp tile 32x64, KC=32 chunks.
__device__ __forceinline__ void split_pack(float x, float y, uint32_t& hi, uint32_t& lo) {
    __nv_bfloat16 hx = __float2bfloat16_rn(x);
    __nv_bfloat16 hy = __float2bfloat16_rn(y);
    __nv_bfloat16 lx = __float2bfloat16_rn(x - __bfloat162float(hx));
    __nv_bfloat16 ly = __float2bfloat16_rn(y - __bfloat162float(hy));
    hi = ((uint32_t)*(uint16_t*)&hy << 16) | *(uint16_t*)&hx;
    lo = ((uint32_t)*(uint16_t*)&ly << 16) | *(uint16_t*)&lx;
}

__device__ __forceinline__ uint32_t smem_u32(const void* p) {
    return (uint32_t)__cvta_generic_to_shared(p);
}

__global__ void __launch_bounds__(256, 2)
k_gemm_tc(const float* __restrict__ A, int lda, const float* __restrict__ W,
          float* __restrict__ C) {
    __shared__ __align__(16) uint16_t sA[2][128 * 40];   // [hi/lo][m][k] stride 40
    __shared__ __align__(16) uint16_t sB[2][32 * 136];   // [hi/lo][k][n] stride 136

    int t = threadIdx.x;
    int m0 = blockIdx.x * 128;
    int wid = t >> 5, lane = t & 31;
    int wm = (wid & 3) * 32, wn = (wid >> 2) * 64;

    float acc[2][8][4];
#pragma unroll
    for (int i = 0; i < 2; i++)
#pragma unroll
        for (int j = 0; j < 8; j++)
#pragma unroll
            for (int q = 0; q < 4; q++) acc[i][j][q] = 0.f;

    // precompute ldmatrix addresses (k-chunk-relative)
    int a_row[2], a_col;
    a_col = (lane >> 4) * 8;                 // + ks*16
#pragma unroll
    for (int mi = 0; mi < 2; mi++) a_row[mi] = wm + mi * 16 + (lane & 15);
    int b_kr = (lane & 7) + ((lane >> 3) & 1) * 8;   // + ks*16
    int b_nc0 = wn + (lane >> 4) * 8;

    for (int kc = 0; kc < 4; kc++) {
        // ---- stage A chunk: rows 128 x k 32 ----
        {
            int r = t >> 1, cq = (t & 1) * 16;
            const float* ap = A + (size_t)(m0 + r) * lda + kc * 32 + cq;
            uint16_t* dh = &sA[0][r * 40 + cq];
            uint16_t* dl = &sA[1][r * 40 + cq];
#pragma unroll
            for (int i = 0; i < 4; i++) {
                float4 v = *(const float4*)(ap + i * 4);
                uint32_t h0, l0, h1, l1;
                split_pack(v.x, v.y, h0, l0);
                split_pack(v.z, v.w, h1, l1);
                ((uint32_t*)(dh + i * 4))[0] = h0;
                ((uint32_t*)(dh + i * 4))[1] = h1;
                ((uint32_t*)(dl + i * 4))[0] = l0;
                ((uint32_t*)(dl + i * 4))[1] = l1;
            }
        }
        // ---- stage B chunk: k 32 x n 128 ----
        {
            int kk = t >> 3, nq = (t & 7) * 16;
            const float* bp = W + (size_t)(kc * 32 + kk) * 128 + nq;
            uint16_t* dh = &sB[0][kk * 136 + nq];
            uint16_t* dl = &sB[1][kk * 136 + nq];
#pragma unroll
            for (int i = 0; i < 4; i++) {
                float4 v = *(const float4*)(bp + i * 4);
                uint32_t h0, l0, h1, l1;
                split_pack(v.x, v.y, h0, l0);
                split_pack(v.z, v.w, h1, l1);
                ((uint32_t*)(dh + i * 4))[0] = h0;
                ((uint32_t*)(dh + i * 4))[1] = h1;
                ((uint32_t*)(dl + i * 4))[0] = l0;
                ((uint32_t*)(dl + i * 4))[1] = l1;
            }
        }
        __syncthreads();

#pragma unroll
        for (int pass = 0; pass < 3; pass++) {
            const uint16_t* aT = sA[pass == 1 ? 1 : 0];
            const uint16_t* bT = sB[pass == 2 ? 1 : 0];
#pragma unroll
            for (int ks = 0; ks < 2; ks++) {
                uint32_t af[2][4];
#pragma unroll
                for (int mi = 0; mi < 2; mi++) {
                    uint32_t addr = smem_u32(aT + a_row[mi] * 40 + ks * 16 + a_col);
                    asm volatile(
                        "ldmatrix.sync.aligned.m8n8.x4.shared.b16 {%0,%1,%2,%3}, [%4];"
                        : "=r"(af[mi][0]), "=r"(af[mi][1]), "=r"(af[mi][2]), "=r"(af[mi][3])
                        : "r"(addr));
                }
                uint32_t bf[8][2];
#pragma unroll
                for (int nt = 0; nt < 4; nt++) {
                    uint32_t addr = smem_u32(bT + (ks * 16 + b_kr) * 136 + nt * 16 + b_nc0);
                    asm volatile(
                        "ldmatrix.sync.aligned.m8n8.x4.trans.shared.b16 {%0,%1,%2,%3}, [%4];"
                        : "=r"(bf[nt * 2][0]), "=r"(bf[nt * 2][1]),
                          "=r"(bf[nt * 2 + 1][0]), "=r"(bf[nt * 2 + 1][1])
                        : "r"(addr));
                }
#pragma unroll
                for (int mi = 0; mi < 2; mi++)
#pragma unroll
                    for (int nj = 0; nj < 8; nj++) {
                        asm volatile(
                            "mma.sync.aligned.m16n8k16.row.col.f32.bf16.bf16.f32 "
                            "{%0,%1,%2,%3}, {%4,%5,%6,%7}, {%8,%9}, {%0,%1,%2,%3};"
                            : "+f"(acc[mi][nj][0]), "+f"(acc[mi][nj][1]),
                              "+f"(acc[mi][nj][2]), "+f"(acc[mi][nj][3])
                            : "r"(af[mi][0]), "r"(af[mi][1]), "r"(af[mi][2]), "r"(af[mi][3]),
                              "r"(bf[nj][0]), "r"(bf[nj][1]));
                    }
            }
        }
        __syncthreads();
    }

    // epilogue: write fp32 C (ldc = 128)
#pragma unroll
    for (int mi = 0; mi < 2; mi++) {
        int row = m0 + wm + mi * 16 + (lane >> 2);
#pragma unroll
        for (int nj = 0; nj < 8; nj++) {
            int col = wn + nj * 8 + (lane & 3) * 2;
            *(float2*)(C + (size_t)row * 128 + col) =
                make_float2(acc[mi][nj][0], acc[mi][nj][1]);
            *(float2*)(C + (size_t)(row + 8) * 128 + col) =
                make_float2(acc[mi][nj][2], acc[mi][nj][3]);
        }
    }
}

// ---------------- SMEM-tile aggregate: per (graph, 64-col half) ----------------
// out[n,c] = relu(bias + dn^2*xw[n,c] + dn * sum_s dis[s]*xw[s,c])
#define AGG_SMEM ((512 * 68 + 512) * 4)
__global__ void __launch_bounds__(512, 1)
k_agg_sm(const float* __restrict__ bias, float* __restrict__ out) {
    extern __shared__ float sm[];
    float* smXW  = sm;                 // [512][68]
    float* smDSS = sm + 512 * 68;      // [512]

    int g = blockIdx.y;
    int c0 = blockIdx.x * 64;
    int tid = threadIdx.x;
    int nb = g * N_PG;

    const float* xw = g_xw;
    for (int i = tid; i < 512 * 16; i += 512) {
        int row = i >> 4, cq = (i & 15) << 2;
        *(float4*)&smXW[row * 68 + cq] =
            *(const float4*)(xw + (size_t)(nb + row) * 128 + c0 + cq);
    }
    if (tid < N_PG) smDSS[tid] = g_dis[nb + tid];
    __syncthreads();

    int cg = tid & 7;            // 8 col groups x 8 cols
    int ng = tid >> 3;           // 64 node groups x 8 nodes
    float4 bb0 = *(const float4*)(bias + c0 + cg * 8);
    float4 bb1 = *(const float4*)(bias + c0 + cg * 8 + 4);

    for (int ii = 0; ii < 8; ii++) {
        int n = ng * 8 + ii;
        float dn = smDSS[n];
        float s2 = dn * dn;
        const float* rn = smXW + n * 68 + cg * 8;
        float4 v0 = *(const float4*)rn;
        float4 v1 = *(const float4*)(rn + 4);
        float4 a0 = make_float4(s2 * v0.x, s2 * v0.y, s2 * v0.z, s2 * v0.w);
        float4 a1 = make_float4(s2 * v1.x, s2 * v1.y, s2 * v1.z, s2 * v1.w);

        int base = g_off[nb + n];
        int d = g_deg[nb + n];
        if (d > 0) {
            int s = g_csr[base];
            float w = dn * smDSS[s];
            const float* r = smXW + s * 68 + cg * 8;
            float4 u0 = *(const float4*)r;
            float4 u1 = *(const float4*)(r + 4);
            for (int j = 0; j < d; j++) {
                float wj = w;
                float4 t0 = u0, t1 = u1;
                if (j + 1 < d) {
                    int s2i = g_csr[base + j + 1];
                    w = dn * smDSS[s2i];
                    const float* r2 = smXW + s2i * 68 + cg * 8;
                    u0 = *(const float4*)r2;
                    u1 = *(const float4*)(r2 + 4);
                }
                a0.x += wj * t0.x; a0.y += wj * t0.y; a0.z += wj * t0.z; a0.w += wj * t0.w;
                a1.x += wj * t1.x; a1.y += wj * t1.y; a1.z += wj * t1.z; a1.w += wj * t1.w;
            }
        }
        float4 o0 = make_float4(fmaxf(a0.x + bb0.x, 0.f), fmaxf(a0.y + bb0.y, 0.f),
                                fmaxf(a0.z + bb0.z, 0.f), fmaxf(a0.w + bb0.w, 0.f));
        float4 o1 = make_float4(fmaxf(a1.x + bb1.x, 0.f), fmaxf(a1.y + bb1.y, 0.f),
                                fmaxf(a1.z + bb1.z, 0.f), fmaxf(a1.w + bb1.w, 0.f));
        float* op = out + (size_t)(nb + n) * 384 + c0 + cg * 8;
        *(float4*)op = o0;
        *(float4*)(op + 4) = o1;
    }
}

// ---------------- fused score GEMV + score aggregate + top-k + gated readout ----------------
__global__ void k_spool(const float* __restrict__ Wsc, const float* __restrict__ bs) {
    __shared__ float ws[384];
    __shared__ float spre[N_PG];
    __shared__ float dss[N_PG];
    __shared__ float scr[N_PG];
    __shared__ unsigned long long key[N_PG];
    __shared__ int sel[K_SEL];
    __shared__ float gate[K_SEL];

    int g = blockIdx.x, t = threadIdx.x;    // 512 threads
    int nb = g * N_PG;
    if (t < 384) ws[t] = Wsc[t];
    dss[t] = g_dis[nb + t];
    __syncthreads();

    int w = t >> 5, lane = t & 31;
    for (int i = 0; i < 32; i++) {
        int n = i * 16 + w;
        const float* h = g_h + (size_t)(nb + n) * 384;
        float acc = 0.f;
#pragma unroll
        for (int c = lane * 4; c < 384; c += 128) {
            float4 hv = *(const float4*)(h + c);
            float4 wv = *(const float4*)(ws + c);
            acc += hv.x * wv.x + hv.y * wv.y + hv.z * wv.z + hv.w * wv.w;
        }
#pragma unroll
        for (int o = 16; o; o >>= 1) acc += __shfl_xor_sync(0xffffffffu, acc, o);
        if (lane == 0) spre[n] = acc;
    }
    __syncthreads();

    float dn = dss[t];
    float sc = dn * dn * spre[t];
    int base = g_off[nb + t], d = g_deg[nb + t];
    for (int j = 0; j < d; j++) {
        int s = g_csr[base + j];
        sc += dn * dss[s] * spre[s];
    }
    sc += bs[0];
    scr[t] = sc;

    unsigned u = __float_as_uint(sc);
    u = (u & 0x80000000u) ? ~u : (u ^ 0x80000000u);
    u = ~u;                                  // descending order
    key[t] = ((unsigned long long)u << 32) | (unsigned)t;
    __syncthreads();

    for (int k = 2; k <= N_PG; k <<= 1) {
        for (int j = k >> 1; j > 0; j >>= 1) {
            int ixj = t ^ j;
            if (ixj > t) {
                unsigned long long a = key[t], b = key[ixj];
                bool up = ((t & k) == 0);
                if ((a > b) == up) { key[t] = b; key[ixj] = a; }
            }
            __syncthreads();
        }
    }

    if (t < K_SEL) {
        int idx = (int)(key[t] & 0xffffffffu);
        sel[t] = idx;
        gate[t] = tanhf(scr[idx]);
    }
    __syncthreads();

    if (t < 384) {
        float vmax = __int_as_float(0xff800000);
        float vsum = 0.f;
        const float* hb = g_h + (size_t)nb * 384;
        for (int i = 0; i < K_SEL; i++) {
            float v = hb[(size_t)sel[i] * 384 + t] * gate[i];
            vmax = fmaxf(vmax, v);
            vsum += v;
        }
        g_read[g * 768 + t] = vmax;
        g_read[g * 768 + 384 + t] = vsum * (1.0f / K_SEL);
    }
}

// ---------------- small SGEMM (MLP head): C = A(MxK)*B(KxN), bias+relu ----------------
__global__ void k_sgemm_br(const float* __restrict__ A, int lda,
                           const float* __restrict__ B, int ldb,
                           const float* __restrict__ bias,
                           float* __restrict__ C, int ldc, int Kdim) {
    __shared__ float As[16][68];
    __shared__ float Bs[16][68];
    int tid = threadIdx.x;
    int tx = tid & 15, ty = tid >> 4;
    int arow = tid >> 2, acol = (tid & 3) * 4;
    int brow = tid >> 4, bcol = (tid & 15) * 4;
    int row0 = blockIdx.y * 64, col0 = blockIdx.x * 64;
    const float* Aptr = A + (size_t)(row0 + arow) * lda + acol;
    const float* Bptr = B + (size_t)brow * ldb + col0 + bcol;
    float acc[4][4];
#pragma unroll
    for (int i = 0; i < 4; i++)
#pragma unroll
        for (int j = 0; j < 4; j++) acc[i][j] = 0.f;
    for (int k0 = 0; k0 < Kdim; k0 += 16) {
        float4 a = *(const float4*)(Aptr + k0);
        float4 b = *(const float4*)(Bptr + (size_t)k0 * ldb);
        As[acol + 0][arow] = a.x; As[acol + 1][arow] = a.y;
        As[acol + 2][arow] = a.z; As[acol + 3][arow] = a.w;
        *(float4*)&Bs[brow][bcol] = b;
        __syncthreads();
#pragma unroll
        for (int k = 0; k < 16; k++) {
            float ar[4], br[4];
            *(float4*)ar = *(const float4*)&As[k][ty * 4];
            *(float4*)br = *(const float4*)&Bs[k][tx * 4];
#pragma unroll
            for (int i = 0; i < 4; i++)
#pragma unroll
                for (int j = 0; j < 4; j++) acc[i][j] += ar[i] * br[j];
        }
        __syncthreads();
    }
#pragma unroll
    for (int i = 0; i < 4; i++)
#pragma unroll
        for (int j = 0; j < 4; j++) {
            int col = col0 + tx * 4 + j;
            C[(size_t)(row0 + ty * 4 + i) * ldc + col] =
                fmaxf(acc[i][j] + bias[col], 0.f);
        }
}

// ---------------- final layer + log_softmax ----------------
__global__ void k_final(const float* __restrict__ Wl3, const float* __restrict__ bl3,
                        float* __restrict__ out) {
    int r = blockIdx.x;
    int lane = threadIdx.x;
    float4 zv = *(const float4*)(g_z2 + r * 128 + lane * 4);
    float logits[10];
#pragma unroll
    for (int o = 0; o < 10; o++) {
        int k = lane * 4;
        float p = zv.x * Wl3[(k + 0) * 10 + o] + zv.y * Wl3[(k + 1) * 10 + o] +
                  zv.z * Wl3[(k + 2) * 10 + o] + zv.w * Wl3[(k + 3) * 10 + o];
#pragma unroll
        for (int s = 16; s; s >>= 1) p += __shfl_xor_sync(0xffffffffu, p, s);
        logits[o] = p + bl3[o];
    }
    if (lane == 0) {
        float m = logits[0];
#pragma unroll
        for (int o = 1; o < 10; o++) m = fmaxf(m, logits[o]);
        float se = 0.f;
#pragma unroll
        for (int o = 0; o < 10; o++) se += expf(logits[o] - m);
        float lse = m + logf(se);
#pragma unroll
        for (int o = 0; o < 10; o++) out[r * 10 + o] = logits[o] - lse;
    }
}

// ---------------- launcher ----------------
extern "C" void kernel_launch(void* const* d_in, const int* in_sizes, int n_in,
                              void* d_out, int out_size) {
    const float* x   = (const float*)d_in[0];
    const int*   ei  = (const int*)d_in[1];
    const float* W1  = (const float*)d_in[2];
    const float* b1  = (const float*)d_in[3];
    const float* W2  = (const float*)d_in[4];
    const float* b2  = (const float*)d_in[5];
    const float* W3  = (const float*)d_in[6];
    const float* b3  = (const float*)d_in[7];
    const float* Ws  = (const float*)d_in[8];
    const float* bs  = (const float*)d_in[9];
    const float* Wl1 = (const float*)d_in[10];
    const float* bl1 = (const float*)d_in[11];
    const float* Wl2 = (const float*)d_in[12];
    const float* bl2 = (const float*)d_in[13];
    const float* Wl3 = (const float*)d_in[14];
    const float* bl3 = (const float*)d_in[15];

    const int* src = ei;
    const int* dst = ei + N_E;

    static int attr_done = 0;
    if (!attr_done) {
        cudaFuncSetAttribute(k_agg_sm, cudaFuncAttributeMaxDynamicSharedMemorySize,
                             AGG_SMEM);
        attr_done = 1;
    }

    void* p;
    cudaGetSymbolAddress(&p, g_xw);   float* xw = (float*)p;
    cudaGetSymbolAddress(&p, g_h);    float* h  = (float*)p;
    cudaGetSymbolAddress(&p, g_read); float* rd = (float*)p;
    cudaGetSymbolAddress(&p, g_z1);   float* z1 = (float*)p;
    cudaGetSymbolAddress(&p, g_z2);   float* z2 = (float*)p;

    k_prep<<<B_G, N_PG>>>(src, dst);

    dim3 ga(2, B_G);
    k_gemm_tc<<<N_NODES / 128, 256>>>(x, 128, W1, xw);
    k_agg_sm<<<ga, 512, AGG_SMEM>>>(b1, h + 0);
    k_gemm_tc<<<N_NODES / 128, 256>>>(h + 0, 384, W2, xw);
    k_agg_sm<<<ga, 512, AGG_SMEM>>>(b2, h + 128);
    k_gemm_tc<<<N_NODES / 128, 256>>>(h + 128, 384, W3, xw);
    k_agg_sm<<<ga, 512, AGG_SMEM>>>(b3, h + 256);

    k_spool<<<B_G, N_PG>>>(Ws, bs);

    k_sgemm_br<<<dim3(4, 2), 256>>>(rd, 768, Wl1, 256, bl1, z1, 256, 768);
    k_sgemm_br<<<dim3(2, 2), 256>>>(z1, 256, Wl2, 128, bl2, z2, 128, 256);
    k_final<<<B_G, 32>>>(Wl3, bl3, (float*)d_out);
}